// round 7
// baseline (speedup 1.0000x reference)
#include <cuda_runtime.h>
#include <cuda_fp16.h>
#include <math.h>

#define Bb 64
#define Nn 1024
#define DEG 8
#define ALPHA 0.2f

// Scratch (static __device__ globals — allocation-free per harness rules)
__device__ float g_s1[Bb * Nn];                         // h @ a1 (fp32)
__device__ float g_s2[Bb * Nn];                         // h @ a2 (fp32)
__device__ __align__(16) __half2 g_h2[Bb * Nn * 32];    // 8 MB: h in fp16 (gather operand)

#define SAT_PITCH 132   // floats per k-row of the A tile (128 rows + pad, 16B-aligned)

__device__ __forceinline__ unsigned h2u(__half2 v) {
    return *reinterpret_cast<unsigned*>(&v);
}
// duplicate a float into a packed (v,v) 64-bit operand for fma.rn.f32x2
__device__ __forceinline__ unsigned long long dup2(float v) {
    unsigned long long r;
    asm("mov.b64 %0, {%1, %1};" : "=l"(r) : "r"(__float_as_uint(v)));
    return r;
}
// packed f32x2 FMA: d.lo += a.lo*b.lo ; d.hi += a.hi*b.hi
__device__ __forceinline__ void fma2(unsigned long long& d,
                                     unsigned long long a,
                                     unsigned long long b) {
    asm("fma.rn.f32x2 %0, %1, %2, %0;" : "+l"(d) : "l"(a), "l"(b));
}
__device__ __forceinline__ float2 up64(unsigned long long v) {
    float2 r;
    r.x = __uint_as_float((unsigned)v);
    r.y = __uint_as_float((unsigned)(v >> 32));
    return r;
}

// ---------------------------------------------------------------------------
// Kernel 1: h = atoms @ W (65536 x 64 x 64) with packed FFMA2.
// Block = 256 threads covers 128 rows. Thread (rg, cg): rows 4*rg..+3,
// cols 8*cg..+7, accumulated as 4x4 f32x2 (row x col-pair).
// Per k: 3 LDS.128 + 4 dup-MOV (alu pipe) + 16 FFMA2 (fma pipe).
// Grid 512, ~50KB smem -> 3 CTAs/SM co-resident; fma-pipe floor ~7.9us.
// Epilogue: h stored fp16; s1/s2 fused (fp32).
// ---------------------------------------------------------------------------
__global__ __launch_bounds__(256) void gat_gemm(const float* __restrict__ atoms,
                                                const float* __restrict__ W,
                                                const float* __restrict__ a)
{
    extern __shared__ __align__(16) float sm[];
    float* sAT = sm;                       // [64 k][SAT_PITCH] transposed atoms
    float* sW  = sm + 64 * SAT_PITCH;      // [64 k][64 c]

    const int tid  = threadIdx.x;
    const int row0 = blockIdx.x * 128;

    #pragma unroll
    for (int i = tid; i < 4096; i += 256) sW[i] = W[i];

    #pragma unroll
    for (int i = tid; i < 8192; i += 256) {
        int r = i >> 6, k = i & 63;
        sAT[k * SAT_PITCH + r] = atoms[(size_t)(row0 + r) * 64 + k];
    }
    __syncthreads();

    const int cg = tid & 7;    // col group: cols 8*cg..+7 (4 pairs)
    const int rg = tid >> 3;   // row group: rows 4*rg..+3

    unsigned long long acc[4][4];
    #pragma unroll
    for (int r = 0; r < 4; r++)
        #pragma unroll
        for (int p = 0; p < 4; p++) acc[r][p] = 0ULL;

    #pragma unroll 4
    for (int k = 0; k < 64; k++) {
        float4 av = *(const float4*)&sAT[k * SAT_PITCH + rg * 4];
        ulonglong2 wp0 = *(const ulonglong2*)&sW[k * 64 + cg * 8];
        ulonglong2 wp1 = *(const ulonglong2*)&sW[k * 64 + cg * 8 + 4];
        unsigned long long a0 = dup2(av.x), a1 = dup2(av.y),
                           a2 = dup2(av.z), a3 = dup2(av.w);
        fma2(acc[0][0], a0, wp0.x); fma2(acc[0][1], a0, wp0.y);
        fma2(acc[0][2], a0, wp1.x); fma2(acc[0][3], a0, wp1.y);
        fma2(acc[1][0], a1, wp0.x); fma2(acc[1][1], a1, wp0.y);
        fma2(acc[1][2], a1, wp1.x); fma2(acc[1][3], a1, wp1.y);
        fma2(acc[2][0], a2, wp0.x); fma2(acc[2][1], a2, wp0.y);
        fma2(acc[2][2], a2, wp1.x); fma2(acc[2][3], a2, wp1.y);
        fma2(acc[3][0], a3, wp0.x); fma2(acc[3][1], a3, wp0.y);
        fma2(acc[3][2], a3, wp1.x); fma2(acc[3][3], a3, wp1.y);
    }

    float a1v[8], a2v[8];
    #pragma unroll
    for (int c = 0; c < 8; c++) {
        a1v[c] = a[cg * 8 + c];
        a2v[c] = a[64 + cg * 8 + c];
    }

    #pragma unroll
    for (int r = 0; r < 4; r++) {
        const int row = row0 + rg * 4 + r;
        float2 u[4];
        #pragma unroll
        for (int p = 0; p < 4; p++) u[p] = up64(acc[r][p]);

        uint4 pk;
        pk.x = h2u(__floats2half2_rn(u[0].x, u[0].y));
        pk.y = h2u(__floats2half2_rn(u[1].x, u[1].y));
        pk.z = h2u(__floats2half2_rn(u[2].x, u[2].y));
        pk.w = h2u(__floats2half2_rn(u[3].x, u[3].y));
        *reinterpret_cast<uint4*>(&g_h2[(size_t)row * 32 + cg * 4]) = pk;

        float p1 = 0.f, p2 = 0.f;
        #pragma unroll
        for (int p = 0; p < 4; p++) {
            p1 = fmaf(u[p].x, a1v[2 * p], p1);     p1 = fmaf(u[p].y, a1v[2 * p + 1], p1);
            p2 = fmaf(u[p].x, a2v[2 * p], p2);     p2 = fmaf(u[p].y, a2v[2 * p + 1], p2);
        }
        #pragma unroll
        for (int off = 4; off > 0; off >>= 1) {     // reduce over the 8 cg lanes
            p1 += __shfl_xor_sync(0xffffffffu, p1, off);
            p2 += __shfl_xor_sync(0xffffffffu, p2, off);
        }
        if (cg == 0) {
            g_s1[row] = p1;
            g_s2[row] = p2;
        }
    }
}

// ---------------------------------------------------------------------------
// Kernel 2: fused softmax-weights + aggregation, h cached in SMEM.
// Grid = 128 (two CTAs per batch, each owns 512 rows), block = 512.
// SMEM: full batch h (fp16, 128KB) + s2 (4KB) + per-row edges (16KB) +
// weights (16KB) = 164KB -> 1 CTA/SM, one wave over 128 SMs.
// Phase A: one THREAD per row computes dedup + leaky + softmax (s2 from smem).
// Phase B: one WARP per row gathers 8 h-rows from SMEM (conflict-free 128B
// per gather), fp32 FMA, ELU, coalesced float2 store.
// ---------------------------------------------------------------------------
#define SH_BYTES   (Nn * 64 * 2)             // 131072: h as half2 (uint)
#define SS2_OFF    SH_BYTES
#define SE_OFF     (SS2_OFF + Nn * 4)        // +4096
#define SWT_OFF    (SE_OFF + 512 * DEG * 4)  // +16384
#define SMEM_BATCH (SWT_OFF + 512 * DEG * 4) // 167936 total

__global__ __launch_bounds__(512) void gat_batch(const int* __restrict__ edges,
                                                 float* __restrict__ out)
{
    extern __shared__ __align__(16) char smc[];
    unsigned* sH  = (unsigned*)smc;                 // [1024 rows][32 half2]
    float*    sS2 = (float*)(smc + SS2_OFF);        // [1024]
    int*      sE  = (int*)(smc + SE_OFF);           // [512][8]
    float*    sWt = (float*)(smc + SWT_OFF);        // [512][8]

    const int tid     = threadIdx.x;
    const int b       = blockIdx.x >> 1;
    const int rowBase = (blockIdx.x & 1) << 9;      // 0 or 512

    // Stage full batch h (128 KB) + s2 into smem, coalesced.
    const uint4* hsrc = (const uint4*)(g_h2 + ((size_t)b << 15));
    uint4* hdst = (uint4*)sH;
    #pragma unroll
    for (int i = tid; i < 8192; i += 512) hdst[i] = hsrc[i];
    ((float2*)sS2)[tid] = ((const float2*)(g_s2 + (b << 10)))[tid];
    __syncthreads();

    // Phase A: per-row softmax weights (one thread per row).
    {
        const int row = rowBase + tid;
        const int g   = (b << 10) + row;
        const int4 ea = __ldg(&((const int4*)edges)[2 * g]);
        const int4 eb = __ldg(&((const int4*)edges)[2 * g + 1]);
        int e[DEG] = { ea.x & (Nn-1), ea.y & (Nn-1), ea.z & (Nn-1), ea.w & (Nn-1),
                       eb.x & (Nn-1), eb.y & (Nn-1), eb.z & (Nn-1), eb.w & (Nn-1) };
        const float s1g = g_s1[g];

        float w[DEG];
        float mx = -1e30f;
        #pragma unroll
        for (int m = 0; m < DEG; m++) {
            float ev = s1g + sS2[e[m]];
            ev = ev > 0.f ? ev : ALPHA * ev;
            bool dup = false;
            #pragma unroll
            for (int n = 0; n < m; n++) dup = dup || (e[n] == e[m]);
            w[m] = dup ? -1e30f : ev;
            mx = fmaxf(mx, w[m]);
        }
        float den = 0.f;
        #pragma unroll
        for (int m = 0; m < DEG; m++) {
            w[m] = (w[m] == -1e30f) ? 0.f : __expf(w[m] - mx);
            den += w[m];
        }
        const float inv = 1.f / den;

        ((int4*)sE)[2 * tid]      = make_int4(e[0], e[1], e[2], e[3]);
        ((int4*)sE)[2 * tid + 1]  = make_int4(e[4], e[5], e[6], e[7]);
        ((float4*)sWt)[2 * tid]     = make_float4(w[0]*inv, w[1]*inv, w[2]*inv, w[3]*inv);
        ((float4*)sWt)[2 * tid + 1] = make_float4(w[4]*inv, w[5]*inv, w[6]*inv, w[7]*inv);
    }
    __syncthreads();

    // Phase B: warp per row, 32 rows per warp; gathers hit the smem crossbar.
    const int warp = tid >> 5;
    const int lane = tid & 31;
    float2* outb = (float2*)out + ((size_t)((b << 10) + rowBase) << 5);

    for (int i = 0; i < 32; i++) {
        const int lr = warp * 32 + i;
        const int4   e0 = ((const int4*)sE)[2 * lr];
        const int4   e1 = ((const int4*)sE)[2 * lr + 1];
        const float4 w0 = ((const float4*)sWt)[2 * lr];
        const float4 w1 = ((const float4*)sWt)[2 * lr + 1];

        float2 acc = make_float2(0.f, 0.f);
        #define GSTEP(E, Wv) { \
            __half2 hv2 = *reinterpret_cast<const __half2*>(&sH[(E) * 32 + lane]); \
            float2 hv = __half22float2(hv2); \
            acc.x = fmaf((Wv), hv.x, acc.x); \
            acc.y = fmaf((Wv), hv.y, acc.y); }
        GSTEP(e0.x, w0.x) GSTEP(e0.y, w0.y) GSTEP(e0.z, w0.z) GSTEP(e0.w, w0.w)
        GSTEP(e1.x, w1.x) GSTEP(e1.y, w1.y) GSTEP(e1.z, w1.z) GSTEP(e1.w, w1.w)
        #undef GSTEP

        float2 o;
        o.x = acc.x > 0.f ? acc.x : expm1f(acc.x);
        o.y = acc.y > 0.f ? acc.y : expm1f(acc.y);
        outb[(size_t)lr * 32 + lane] = o;
    }
}

// ---------------------------------------------------------------------------
extern "C" void kernel_launch(void* const* d_in, const int* in_sizes, int n_in,
                              void* d_out, int out_size) {
    // Bind inputs BY ELEMENT COUNT (all four sizes distinct) — order-proof.
    const float* atoms = nullptr;   // 64*1024*64 = 4194304 (f32)
    const int*   edges = nullptr;   // 64*1024*8  = 524288  (i32: jax x64 off)
    const float* W     = nullptr;   // 64*64      = 4096    (f32)
    const float* a     = nullptr;   // 2*64*1     = 128     (f32)

    for (int i = 0; i < n_in; i++) {
        switch (in_sizes[i]) {
            case 4194304: atoms = (const float*)d_in[i]; break;
            case 524288:  edges = (const int*)d_in[i];   break;
            case 4096:    W     = (const float*)d_in[i]; break;
            case 128:     a     = (const float*)d_in[i]; break;
            default: break;
        }
    }
    if (!atoms || !edges || !W || !a) return;

    float* out = (float*)d_out;

    const int smem_gemm = (64 * SAT_PITCH + 64 * 64) * sizeof(float);  // 50176 B
    cudaFuncSetAttribute(gat_gemm, cudaFuncAttributeMaxDynamicSharedMemorySize, smem_gemm);
    cudaFuncSetAttribute(gat_batch, cudaFuncAttributeMaxDynamicSharedMemorySize, SMEM_BATCH);

    gat_gemm<<<(Bb * Nn) / 128, 256, smem_gemm>>>(atoms, W, a);
    gat_batch<<<Bb * 2, 512, SMEM_BATCH>>>(edges, out);
}

// round 9
// speedup vs baseline: 1.0486x; 1.0486x over previous
#include <cuda_runtime.h>
#include <cuda_fp16.h>
#include <math.h>

#define Bb 64
#define Nn 1024
#define DEG 8
#define ALPHA 0.2f

#define TILE_ROWS 32
#define NTILES 2048          // 65536 rows / 32
#define GEMM_GRID 304        // ~2 CTAs per SM; any value is correct (queue)

// Scratch (static __device__ globals — allocation-free per harness rules)
__device__ float g_s1[Bb * Nn];                         // h @ a1 (fp32)
__device__ float g_s2[Bb * Nn];                         // h @ a2 (fp32)
__device__ __align__(16) float   g_w[Bb * Nn * DEG];    // normalized softmax weights
__device__ __align__(16) __half2 g_h2[Bb * Nn * 32];    // 8 MB: h in fp16 (gather operand)
__device__ unsigned g_ctr;                              // tile queue head (reset by gat_weights)

// ---------------------------------------------------------------------------
// Kernel 1: h = atoms @ W (65536 x 64 x 64). Persistent CTAs + atomic tile
// queue (32-row tiles) for near-perfect SM balance. Per warp: rows 4w..4w+3,
// lane owns cols {2*lane, 2*lane+1}. Per k: 1 broadcast LDS.128 (A) +
// 1 LDS.64 (W) + 8 FFMA -> FFMA-dominant issue mix. Next tile is prefetched
// into registers during compute, then staged to the alternate smem buffer.
// Epilogue: h stored fp16; s1/s2 fused (fp32, full-warp butterfly).
// ---------------------------------------------------------------------------
__global__ __launch_bounds__(256) void gat_gemm(const float* __restrict__ atoms,
                                                const float* __restrict__ W,
                                                const float* __restrict__ a)
{
    __shared__ __align__(16) float sW[64 * 64];        // [k][c]
    __shared__ __align__(16) float sA[2][64 * 36];     // [buf][k][r(32)+pad4]
    __shared__ unsigned s_tile;

    const int tid  = threadIdx.x;
    const int lane = tid & 31;
    const int w    = tid >> 5;          // warp 0..7 -> rows 4w..4w+3

    #pragma unroll
    for (int i = tid; i < 4096; i += 256) sW[i] = W[i];

    const float a10 = a[2 * lane],      a11 = a[2 * lane + 1];
    const float a20 = a[64 + 2 * lane], a21 = a[64 + 2 * lane + 1];

    if (tid == 0) s_tile = atomicAdd(&g_ctr, 1u);
    __syncthreads();
    unsigned t = s_tile;

    if (t < NTILES) {
        const int row0 = t * TILE_ROWS;
        #pragma unroll
        for (int j = 0; j < 8; j++) {
            int i = tid + j * 256, r = i >> 6, k = i & 63;
            sA[0][k * 36 + r] = atoms[(size_t)(row0 + r) * 64 + k];
        }
    }
    __syncthreads();

    int buf = 0;
    while (t < NTILES) {
        if (tid == 0) s_tile = atomicAdd(&g_ctr, 1u);
        __syncthreads();
        const unsigned tn = s_tile;

        float pre[8];
        if (tn < NTILES) {
            const int row0n = tn * TILE_ROWS;
            #pragma unroll
            for (int j = 0; j < 8; j++) {
                int i = tid + j * 256, r = i >> 6, k = i & 63;
                pre[j] = atoms[(size_t)(row0n + r) * 64 + k];
            }
        }

        // ---- compute current tile ----
        float acc[4][2];
        #pragma unroll
        for (int i = 0; i < 4; i++) { acc[i][0] = 0.f; acc[i][1] = 0.f; }

        const float* sAb = &sA[buf][0];
        #pragma unroll 8
        for (int k = 0; k < 64; k++) {
            float4 av = *(const float4*)&sAb[k * 36 + 4 * w];     // broadcast
            float2 wv = *(const float2*)&sW[k * 64 + 2 * lane];
            acc[0][0] = fmaf(av.x, wv.x, acc[0][0]); acc[0][1] = fmaf(av.x, wv.y, acc[0][1]);
            acc[1][0] = fmaf(av.y, wv.x, acc[1][0]); acc[1][1] = fmaf(av.y, wv.y, acc[1][1]);
            acc[2][0] = fmaf(av.z, wv.x, acc[2][0]); acc[2][1] = fmaf(av.z, wv.y, acc[2][1]);
            acc[3][0] = fmaf(av.w, wv.x, acc[3][0]); acc[3][1] = fmaf(av.w, wv.y, acc[3][1]);
        }

        // ---- epilogue ----
        const int row0 = t * TILE_ROWS;
        #pragma unroll
        for (int i = 0; i < 4; i++) {
            const int row = row0 + 4 * w + i;
            g_h2[(size_t)row * 32 + lane] = __floats2half2_rn(acc[i][0], acc[i][1]);

            float p1 = fmaf(acc[i][1], a11, acc[i][0] * a10);
            float p2 = fmaf(acc[i][1], a21, acc[i][0] * a20);
            #pragma unroll
            for (int off = 16; off > 0; off >>= 1) {
                p1 += __shfl_xor_sync(0xffffffffu, p1, off);
                p2 += __shfl_xor_sync(0xffffffffu, p2, off);
            }
            if (lane == 0) {
                g_s1[row] = p1;
                g_s2[row] = p2;
            }
        }

        if (tn >= NTILES) break;

        // ---- stage prefetched tile into the other buffer ----
        #pragma unroll
        for (int j = 0; j < 8; j++) {
            int i = tid + j * 256, r = i >> 6, k = i & 63;
            sA[buf ^ 1][k * 36 + r] = pre[j];
        }
        __syncthreads();
        buf ^= 1;
        t = tn;
    }
}

// ---------------------------------------------------------------------------
// Kernel 2: per-row softmax weight precompute (one thread per row) + queue
// reset for the next graph replay. Dedup + leaky-relu + softmax over <=8
// unique neighbors; -9e15 mask underflows to exact 0 after exp in fp32, so
// this equals the dense reference softmax.
// ---------------------------------------------------------------------------
__global__ __launch_bounds__(256) void gat_weights(const int* __restrict__ edges)
{
    if (blockIdx.x == 0 && threadIdx.x == 0) g_ctr = 0u;   // rearm gemm queue

    const int g = blockIdx.x * 256 + threadIdx.x;      // row in [0, 65536)
    const int b = g >> 10;
    const float* s2b = g_s2 + (b << 10);

    const int4 ea = __ldg(&((const int4*)edges)[2 * g]);
    const int4 eb = __ldg(&((const int4*)edges)[2 * g + 1]);
    int e[DEG] = { ea.x & (Nn - 1), ea.y & (Nn - 1), ea.z & (Nn - 1), ea.w & (Nn - 1),
                   eb.x & (Nn - 1), eb.y & (Nn - 1), eb.z & (Nn - 1), eb.w & (Nn - 1) };

    const float s1g = g_s1[g];

    float w[DEG];
    float mx = -1e30f;
    #pragma unroll
    for (int m = 0; m < DEG; m++) {
        float ev = s1g + __ldg(&s2b[e[m]]);
        ev = ev > 0.f ? ev : ALPHA * ev;
        bool dup = false;
        #pragma unroll
        for (int n = 0; n < m; n++) dup = dup || (e[n] == e[m]);
        w[m] = dup ? -1e30f : ev;
        mx = fmaxf(mx, w[m]);
    }
    float den = 0.f;
    #pragma unroll
    for (int m = 0; m < DEG; m++) {
        w[m] = (w[m] == -1e30f) ? 0.f : __expf(w[m] - mx);
        den += w[m];
    }
    const float inv = 1.f / den;

    ((float4*)g_w)[2 * g]     = make_float4(w[0] * inv, w[1] * inv, w[2] * inv, w[3] * inv);
    ((float4*)g_w)[2 * g + 1] = make_float4(w[4] * inv, w[5] * inv, w[6] * inv, w[7] * inv);
}

// ---------------------------------------------------------------------------
// Kernel 3: aggregation, TWO rows per warp (16 independent gathers in flight
// -> 2x the MLP of one-row-per-warp, which was latency-bound). Edges+weights
// via uniform vector loads; lane owns cols {2*lane, 2*lane+1} of each row.
// Fast ELU via __expf.
// ---------------------------------------------------------------------------
__global__ __launch_bounds__(256) void gat_agg(const int* __restrict__ edges,
                                               float* __restrict__ out)
{
    const int wid  = (blockIdx.x * 256 + threadIdx.x) >> 5;   // 0..32767
    const int lane = threadIdx.x & 31;
    const int g0   = wid * 2;                                  // rows g0, g0+1 (same batch)
    const int b    = g0 >> 10;

    const __half2* hb = g_h2 + ((size_t)b << 15);

    const float4 wa0 = __ldg(&((const float4*)g_w)[2 * g0]);
    const float4 wb0 = __ldg(&((const float4*)g_w)[2 * g0 + 1]);
    const float4 wa1 = __ldg(&((const float4*)g_w)[2 * g0 + 2]);
    const float4 wb1 = __ldg(&((const float4*)g_w)[2 * g0 + 3]);
    const int4 ea0 = __ldg(&((const int4*)edges)[2 * g0]);
    const int4 eb0 = __ldg(&((const int4*)edges)[2 * g0 + 1]);
    const int4 ea1 = __ldg(&((const int4*)edges)[2 * g0 + 2]);
    const int4 eb1 = __ldg(&((const int4*)edges)[2 * g0 + 3]);

    float2 acc0 = make_float2(0.f, 0.f);
    float2 acc1 = make_float2(0.f, 0.f);
    #define GSTEP(ACC, E, Wv) { \
        const float2 hv = __half22float2(__ldg(&hb[(size_t)((E) & (Nn - 1)) * 32 + lane])); \
        ACC.x = fmaf((Wv), hv.x, ACC.x); \
        ACC.y = fmaf((Wv), hv.y, ACC.y); }
    GSTEP(acc0, ea0.x, wa0.x) GSTEP(acc1, ea1.x, wa1.x)
    GSTEP(acc0, ea0.y, wa0.y) GSTEP(acc1, ea1.y, wa1.y)
    GSTEP(acc0, ea0.z, wa0.z) GSTEP(acc1, ea1.z, wa1.z)
    GSTEP(acc0, ea0.w, wa0.w) GSTEP(acc1, ea1.w, wa1.w)
    GSTEP(acc0, eb0.x, wb0.x) GSTEP(acc1, eb1.x, wb1.x)
    GSTEP(acc0, eb0.y, wb0.y) GSTEP(acc1, eb1.y, wb1.y)
    GSTEP(acc0, eb0.z, wb0.z) GSTEP(acc1, eb1.z, wb1.z)
    GSTEP(acc0, eb0.w, wb0.w) GSTEP(acc1, eb1.w, wb1.w)
    #undef GSTEP

    float2 o0, o1;
    o0.x = acc0.x > 0.f ? acc0.x : (__expf(acc0.x) - 1.f);
    o0.y = acc0.y > 0.f ? acc0.y : (__expf(acc0.y) - 1.f);
    o1.x = acc1.x > 0.f ? acc1.x : (__expf(acc1.x) - 1.f);
    o1.y = acc1.y > 0.f ? acc1.y : (__expf(acc1.y) - 1.f);
    ((float2*)out)[(size_t)g0 * 32 + lane]       = o0;
    ((float2*)out)[(size_t)(g0 + 1) * 32 + lane] = o1;
}

// ---------------------------------------------------------------------------
extern "C" void kernel_launch(void* const* d_in, const int* in_sizes, int n_in,
                              void* d_out, int out_size) {
    // Bind inputs BY ELEMENT COUNT (all four sizes distinct) — order-proof.
    const float* atoms = nullptr;   // 64*1024*64 = 4194304 (f32)
    const int*   edges = nullptr;   // 64*1024*8  = 524288  (i32: jax x64 off)
    const float* W     = nullptr;   // 64*64      = 4096    (f32)
    const float* a     = nullptr;   // 2*64*1     = 128     (f32)

    for (int i = 0; i < n_in; i++) {
        switch (in_sizes[i]) {
            case 4194304: atoms = (const float*)d_in[i]; break;
            case 524288:  edges = (const int*)d_in[i];   break;
            case 4096:    W     = (const float*)d_in[i]; break;
            case 128:     a     = (const float*)d_in[i]; break;
            default: break;
        }
    }
    if (!atoms || !edges || !W || !a) return;

    float* out = (float*)d_out;

    gat_gemm<<<GEMM_GRID, 256>>>(atoms, W, a);
    gat_weights<<<(Bb * Nn) / 256, 256>>>(edges);
    gat_agg<<<(Bb * Nn) / 2 / 8, 256>>>(edges, out);
}

// round 12
// speedup vs baseline: 1.1716x; 1.1172x over previous
#include <cuda_runtime.h>
#include <cuda_fp16.h>
#include <cuda_bf16.h>
#include <math.h>
#include <cstdint>

#define Bb 64
#define Nn 1024
#define DEG 8
#define ALPHA 0.2f

// ---------------- scratch ---------------------------------------------------
__device__ float g_s1[Bb * Nn];
__device__ float g_s2[Bb * Nn];
__device__ __align__(16) float   g_w[Bb * Nn * DEG];
__device__ __align__(16) __half2 g_h2[Bb * Nn * 32];

__device__ __forceinline__ unsigned h2u(__half2 v) { return *reinterpret_cast<unsigned*>(&v); }
__device__ __forceinline__ unsigned pack_bf16(float x, float y) {
    __nv_bfloat162 t;
    t.x = __float2bfloat16(x);
    t.y = __float2bfloat16(y);
    return *reinterpret_cast<unsigned*>(&t);
}

// mma.sync m16n8k16 row.col bf16 -> f32 (sm_80+ baseline PTX; HMMA in SASS)
__device__ __forceinline__ void mma16816(float c[4], uint32_t a0, uint32_t a1,
                                         uint32_t a2, uint32_t a3,
                                         uint32_t b0, uint32_t b1) {
    asm volatile(
        "mma.sync.aligned.m16n8k16.row.col.f32.bf16.bf16.f32 "
        "{%0,%1,%2,%3}, {%4,%5,%6,%7}, {%8,%9}, {%0,%1,%2,%3};"
        : "+f"(c[0]), "+f"(c[1]), "+f"(c[2]), "+f"(c[3])
        : "r"(a0), "r"(a1), "r"(a2), "r"(a3), "r"(b0), "r"(b1));
}

// smem word-offsets (uints). Pitch 33 words per row kills tg-bank conflicts.
#define AH_OFF 0
#define AL_OFF (128 * 33)                 // 4224
#define WH_OFF (AL_OFF + 128 * 33)        // 8448
#define WL_OFF (WH_OFF + 64 * 33)         // 10560
#define A1_OFF (WL_OFF + 64 * 33)         // 12672 (floats)
#define A2_OFF (A1_OFF + 64)
#define SMEM_WORDS (A2_OFF + 64)          // 12800 -> 51200 B

// ---------------------------------------------------------------------------
// Kernel 1: h = atoms @ W via bf16-split warp MMA (m16n8k16).
// CTA 256 thr = 8 warps = 128 rows; warp: 16 rows x 64 cols (8 n-tiles).
// D = Ahi*Bhi + Ahi*Blo + Alo*Bhi, fp32 accum.  Epilogue: fp16 h store +
// s1/s2 dots (quad shfl reduce).
// ---------------------------------------------------------------------------
__global__ __launch_bounds__(256) void gat_gemm_mma(const float* __restrict__ atoms,
                                                    const float* __restrict__ W,
                                                    const float* __restrict__ avec)
{
    extern __shared__ __align__(16) unsigned smu[];
    unsigned* aH = smu + AH_OFF;   // [128 rows][33] words: word j = bf16hi(cols 2j,2j+1)
    unsigned* aL = smu + AL_OFF;
    unsigned* wH = smu + WH_OFF;   // [64 n][33] words: word j = bf16hi(W[2j][n], W[2j+1][n])
    unsigned* wL = smu + WL_OFF;
    float*    sa1 = (float*)(smu + A1_OFF);
    float*    sa2 = (float*)(smu + A2_OFF);

    const int tid  = threadIdx.x;
    const int row0 = blockIdx.x * 128;

    // Stage atoms (128 rows x 32 packed words) split hi/lo.
    for (int i = tid; i < 4096; i += 256) {
        const int r = i >> 5, j = i & 31;
        const float2 v = *reinterpret_cast<const float2*>(atoms + (size_t)(row0 + r) * 64 + 2 * j);
        const unsigned hi = pack_bf16(v.x, v.y);
        __nv_bfloat162 hb = *reinterpret_cast<const __nv_bfloat162*>(&hi);
        aH[r * 33 + j] = hi;
        aL[r * 33 + j] = pack_bf16(v.x - __bfloat162float(hb.x),
                                   v.y - __bfloat162float(hb.y));
    }
    // Stage W^T split hi/lo: wH[n][j] packs (W[2j][n], W[2j+1][n]).
    for (int i = tid; i < 2048; i += 256) {
        const int n = i & 63, j = i >> 6;
        const float v0 = W[(2 * j) * 64 + n];
        const float v1 = W[(2 * j + 1) * 64 + n];
        const unsigned hi = pack_bf16(v0, v1);
        __nv_bfloat162 hb = *reinterpret_cast<const __nv_bfloat162*>(&hi);
        wH[n * 33 + j] = hi;
        wL[n * 33 + j] = pack_bf16(v0 - __bfloat162float(hb.x),
                                   v1 - __bfloat162float(hb.y));
    }
    if (tid < 64)       sa1[tid] = avec[tid];
    else if (tid < 128) sa2[tid - 64] = avec[tid];
    __syncthreads();

    const int warp = tid >> 5;           // rows 16*warp .. +15 (within CTA)
    const int lane = tid & 31;
    const int g    = lane >> 2;          // 0..7
    const int tg   = lane & 3;           // 0..3
    const int r0   = warp * 16;

    float c[8][4];                       // [n-tile][c0..c3]
    #pragma unroll
    for (int nt = 0; nt < 8; nt++)
        #pragma unroll
        for (int q = 0; q < 4; q++) c[nt][q] = 0.f;

    #pragma unroll
    for (int kc = 0; kc < 4; kc++) {     // k chunks of 16
        const int base = kc * 8;
        const unsigned* aHr0 = &aH[(r0 + g) * 33 + base + tg];
        const unsigned* aHr8 = &aH[(r0 + g + 8) * 33 + base + tg];
        const unsigned* aLr0 = &aL[(r0 + g) * 33 + base + tg];
        const unsigned* aLr8 = &aL[(r0 + g + 8) * 33 + base + tg];
        const uint32_t ah0 = aHr0[0], ah1 = aHr8[0], ah2 = aHr0[4], ah3 = aHr8[4];
        const uint32_t al0 = aLr0[0], al1 = aLr8[0], al2 = aLr0[4], al3 = aLr8[4];

        #pragma unroll
        for (int nt = 0; nt < 8; nt++) {
            const unsigned* wHn = &wH[(nt * 8 + g) * 33 + base + tg];
            const unsigned* wLn = &wL[(nt * 8 + g) * 33 + base + tg];
            const uint32_t bh0 = wHn[0], bh1 = wHn[4];
            const uint32_t bl0 = wLn[0], bl1 = wLn[4];
            mma16816(c[nt], ah0, ah1, ah2, ah3, bh0, bh1);   // hi*hi
            mma16816(c[nt], ah0, ah1, ah2, ah3, bl0, bl1);   // hi*lo
            mma16816(c[nt], al0, al1, al2, al3, bh0, bh1);   // lo*hi
        }
    }

    // Epilogue. Thread owns rows (r0+g) and (r0+g+8); per n-tile cols
    // {nt*8+2tg, nt*8+2tg+1}: c0,c1 = row g; c2,c3 = row g+8.
    const int rowA = row0 + r0 + g;
    const int rowB = rowA + 8;

    float p1A = 0.f, p2A = 0.f, p1B = 0.f, p2B = 0.f;
    #pragma unroll
    for (int nt = 0; nt < 8; nt++) {
        const int col = nt * 8 + 2 * tg;
        const float w1a = sa1[col], w1b = sa1[col + 1];
        const float w2a = sa2[col], w2b = sa2[col + 1];
        p1A = fmaf(c[nt][0], w1a, p1A);  p1A = fmaf(c[nt][1], w1b, p1A);
        p2A = fmaf(c[nt][0], w2a, p2A);  p2A = fmaf(c[nt][1], w2b, p2A);
        p1B = fmaf(c[nt][2], w1a, p1B);  p1B = fmaf(c[nt][3], w1b, p1B);
        p2B = fmaf(c[nt][2], w2a, p2B);  p2B = fmaf(c[nt][3], w2b, p2B);

        g_h2[(size_t)rowA * 32 + nt * 4 + tg] = __floats2half2_rn(c[nt][0], c[nt][1]);
        g_h2[(size_t)rowB * 32 + nt * 4 + tg] = __floats2half2_rn(c[nt][2], c[nt][3]);
    }
    // Reduce over the 4 tg lanes of each quad.
    #pragma unroll
    for (int off = 1; off <= 2; off <<= 1) {
        p1A += __shfl_xor_sync(0xffffffffu, p1A, off);
        p2A += __shfl_xor_sync(0xffffffffu, p2A, off);
        p1B += __shfl_xor_sync(0xffffffffu, p1B, off);
        p2B += __shfl_xor_sync(0xffffffffu, p2B, off);
    }
    if (tg == 0) {
        g_s1[rowA] = p1A;  g_s2[rowA] = p2A;
        g_s1[rowB] = p1B;  g_s2[rowB] = p2B;
    }
}

// ---------------------------------------------------------------------------
// Kernel 2: per-row softmax weights (one thread per row). Dedup + leaky-relu
// + softmax over <=8 unique neighbors (mask -9e15 underflows to exact 0).
// ---------------------------------------------------------------------------
__global__ __launch_bounds__(256) void gat_weights(const int* __restrict__ edges)
{
    const int g = blockIdx.x * 256 + threadIdx.x;
    const int b = g >> 10;
    const float* s2b = g_s2 + (b << 10);

    const int4 ea = __ldg(&((const int4*)edges)[2 * g]);
    const int4 eb = __ldg(&((const int4*)edges)[2 * g + 1]);
    int e[DEG] = { ea.x & (Nn - 1), ea.y & (Nn - 1), ea.z & (Nn - 1), ea.w & (Nn - 1),
                   eb.x & (Nn - 1), eb.y & (Nn - 1), eb.z & (Nn - 1), eb.w & (Nn - 1) };

    const float s1g = g_s1[g];

    float w[DEG];
    float mx = -1e30f;
    #pragma unroll
    for (int m = 0; m < DEG; m++) {
        float ev = s1g + __ldg(&s2b[e[m]]);
        ev = ev > 0.f ? ev : ALPHA * ev;
        bool dup = false;
        #pragma unroll
        for (int n = 0; n < m; n++) dup = dup || (e[n] == e[m]);
        w[m] = dup ? -1e30f : ev;
        mx = fmaxf(mx, w[m]);
    }
    float den = 0.f;
    #pragma unroll
    for (int m = 0; m < DEG; m++) {
        w[m] = (w[m] == -1e30f) ? 0.f : __expf(w[m] - mx);
        den += w[m];
    }
    const float inv = 1.f / den;

    ((float4*)g_w)[2 * g]     = make_float4(w[0] * inv, w[1] * inv, w[2] * inv, w[3] * inv);
    ((float4*)g_w)[2 * g + 1] = make_float4(w[4] * inv, w[5] * inv, w[6] * inv, w[7] * inv);
}

// ---------------------------------------------------------------------------
// Kernel 3: aggregation, two rows per warp (16 gathers in flight).
// ---------------------------------------------------------------------------
__global__ __launch_bounds__(256) void gat_agg(const int* __restrict__ edges,
                                               float* __restrict__ out)
{
    const int wid  = (blockIdx.x * 256 + threadIdx.x) >> 5;
    const int lane = threadIdx.x & 31;
    const int g0   = wid * 2;
    const int b    = g0 >> 10;

    const __half2* hb = g_h2 + ((size_t)b << 15);

    const float4 wa0 = __ldg(&((const float4*)g_w)[2 * g0]);
    const float4 wb0 = __ldg(&((const float4*)g_w)[2 * g0 + 1]);
    const float4 wa1 = __ldg(&((const float4*)g_w)[2 * g0 + 2]);
    const float4 wb1 = __ldg(&((const float4*)g_w)[2 * g0 + 3]);
    const int4 ea0 = __ldg(&((const int4*)edges)[2 * g0]);
    const int4 eb0 = __ldg(&((const int4*)edges)[2 * g0 + 1]);
    const int4 ea1 = __ldg(&((const int4*)edges)[2 * g0 + 2]);
    const int4 eb1 = __ldg(&((const int4*)edges)[2 * g0 + 3]);

    float2 acc0 = make_float2(0.f, 0.f);
    float2 acc1 = make_float2(0.f, 0.f);
    #define GSTEP(ACC, E, Wv) { \
        const float2 hv = __half22float2(__ldg(&hb[(size_t)((E) & (Nn - 1)) * 32 + lane])); \
        ACC.x = fmaf((Wv), hv.x, ACC.x); \
        ACC.y = fmaf((Wv), hv.y, ACC.y); }
    GSTEP(acc0, ea0.x, wa0.x) GSTEP(acc1, ea1.x, wa1.x)
    GSTEP(acc0, ea0.y, wa0.y) GSTEP(acc1, ea1.y, wa1.y)
    GSTEP(acc0, ea0.z, wa0.z) GSTEP(acc1, ea1.z, wa1.z)
    GSTEP(acc0, ea0.w, wa0.w) GSTEP(acc1, ea1.w, wa1.w)
    GSTEP(acc0, eb0.x, wb0.x) GSTEP(acc1, eb1.x, wb1.x)
    GSTEP(acc0, eb0.y, wb0.y) GSTEP(acc1, eb1.y, wb1.y)
    GSTEP(acc0, eb0.z, wb0.z) GSTEP(acc1, eb1.z, wb1.z)
    GSTEP(acc0, eb0.w, wb0.w) GSTEP(acc1, eb1.w, wb1.w)
    #undef GSTEP

    float2 o0, o1;
    o0.x = acc0.x > 0.f ? acc0.x : (__expf(acc0.x) - 1.f);
    o0.y = acc0.y > 0.f ? acc0.y : (__expf(acc0.y) - 1.f);
    o1.x = acc1.x > 0.f ? acc1.x : (__expf(acc1.x) - 1.f);
    o1.y = acc1.y > 0.f ? acc1.y : (__expf(acc1.y) - 1.f);
    ((float2*)out)[(size_t)g0 * 32 + lane]       = o0;
    ((float2*)out)[(size_t)(g0 + 1) * 32 + lane] = o1;
}

// ---------------------------------------------------------------------------
extern "C" void kernel_launch(void* const* d_in, const int* in_sizes, int n_in,
                              void* d_out, int out_size) {
    const float* atoms = nullptr;   // 4194304 f32
    const int*   edges = nullptr;   // 524288  i32
    const float* W     = nullptr;   // 4096    f32
    const float* a     = nullptr;   // 128     f32

    for (int i = 0; i < n_in; i++) {
        switch (in_sizes[i]) {
            case 4194304: atoms = (const float*)d_in[i]; break;
            case 524288:  edges = (const int*)d_in[i];   break;
            case 4096:    W     = (const float*)d_in[i]; break;
            case 128:     a     = (const float*)d_in[i]; break;
            default: break;
        }
    }
    if (!atoms || !edges || !W || !a) return;

    float* out = (float*)d_out;

    const int smem = SMEM_WORDS * 4;   // 51200 B
    cudaFuncSetAttribute(gat_gemm_mma, cudaFuncAttributeMaxDynamicSharedMemorySize, smem);

    gat_gemm_mma<<<(Bb * Nn) / 128, 256, smem>>>(atoms, W, a);
    gat_weights<<<(Bb * Nn) / 256, 256>>>(edges);
    gat_agg<<<(Bb * Nn) / 2 / 8, 256>>>(edges, out);
}

// round 13
// speedup vs baseline: 1.3067x; 1.1154x over previous
#include <cuda_runtime.h>
#include <cuda_fp16.h>
#include <math.h>

#define Bb 64
#define Nn 1024
#define DEG 8
#define ALPHA 0.2f

// Scratch (static __device__ globals — allocation-free per harness rules)
__device__ float g_s1[Bb * Nn];                         // h @ a1 (fp32)
__device__ float g_s2[Bb * Nn];                         // h @ a2 (fp32)
__device__ __align__(16) float   g_w[Bb * Nn * DEG];    // normalized softmax weights
__device__ __align__(16) __half2 g_h2[Bb * Nn * 32];    // 8 MB: h in fp16 (gather operand)

#define SAT_PITCH 260   // floats; 16B-aligned rows, spreads banks

__device__ __forceinline__ unsigned h2u(__half2 v) {
    return *reinterpret_cast<unsigned*>(&v);
}

// ---------------------------------------------------------------------------
// Kernel 1 (R6, measured 20.3us): h = atoms @ W, scalar FFMA, 8x8 per thread.
// Block = 256 threads covers 256 rows x 64 cols. Inner loop: 4 LDS.128 +
// 64 FFMA per k. Epilogue: fp16 h store (coalesced uint4) + fused s1/s2.
// ---------------------------------------------------------------------------
__global__ __launch_bounds__(256) void gat_gemm(const float* __restrict__ atoms,
                                                const float* __restrict__ W,
                                                const float* __restrict__ a)
{
    extern __shared__ __align__(16) float sm[];
    float* sAT = sm;                       // [64 k][SAT_PITCH] (row-transposed atoms)
    float* sW  = sm + 64 * SAT_PITCH;      // [64 k][64 c]

    const int tid  = threadIdx.x;
    const int row0 = blockIdx.x * 256;

    #pragma unroll
    for (int i = tid; i < 4096; i += 256) sW[i] = W[i];

    #pragma unroll
    for (int i = tid; i < 16384; i += 256) {
        int r = i >> 6, k = i & 63;
        sAT[k * SAT_PITCH + r] = atoms[(size_t)(row0 + r) * 64 + k];
    }
    __syncthreads();

    const int cg = tid & 7;    // col group: cols 8*cg..+7
    const int rg = tid >> 3;   // row group: rows 8*rg..+7

    float acc[8][8];
    #pragma unroll
    for (int r = 0; r < 8; r++)
        #pragma unroll
        for (int c = 0; c < 8; c++) acc[r][c] = 0.f;

    #pragma unroll 4
    for (int k = 0; k < 64; k++) {
        const float* Ak = &sAT[k * SAT_PITCH + rg * 8];
        const float* Wk = &sW[k * 64 + cg * 8];
        float4 a0 = *(const float4*)(Ak);
        float4 a1 = *(const float4*)(Ak + 4);
        float4 w0 = *(const float4*)(Wk);
        float4 w1 = *(const float4*)(Wk + 4);
        float ar[8] = {a0.x, a0.y, a0.z, a0.w, a1.x, a1.y, a1.z, a1.w};
        float wr[8] = {w0.x, w0.y, w0.z, w0.w, w1.x, w1.y, w1.z, w1.w};
        #pragma unroll
        for (int r = 0; r < 8; r++)
            #pragma unroll
            for (int c = 0; c < 8; c++)
                acc[r][c] = fmaf(ar[r], wr[c], acc[r][c]);
    }

    float a1v[8], a2v[8];
    #pragma unroll
    for (int c = 0; c < 8; c++) {
        a1v[c] = a[cg * 8 + c];
        a2v[c] = a[64 + cg * 8 + c];
    }

    #pragma unroll
    for (int r = 0; r < 8; r++) {
        const int row = row0 + rg * 8 + r;

        uint4 pk;
        pk.x = h2u(__floats2half2_rn(acc[r][0], acc[r][1]));
        pk.y = h2u(__floats2half2_rn(acc[r][2], acc[r][3]));
        pk.z = h2u(__floats2half2_rn(acc[r][4], acc[r][5]));
        pk.w = h2u(__floats2half2_rn(acc[r][6], acc[r][7]));
        *reinterpret_cast<uint4*>(&g_h2[(size_t)row * 32 + cg * 4]) = pk;

        float p1 = 0.f, p2 = 0.f;
        #pragma unroll
        for (int c = 0; c < 8; c++) {
            p1 = fmaf(acc[r][c], a1v[c], p1);
            p2 = fmaf(acc[r][c], a2v[c], p2);
        }
        #pragma unroll
        for (int off = 4; off > 0; off >>= 1) {
            p1 += __shfl_xor_sync(0xffffffffu, p1, off);
            p2 += __shfl_xor_sync(0xffffffffu, p2, off);
        }
        if (cg == 0) {
            g_s1[row] = p1;
            g_s2[row] = p2;
        }
    }
}

// ---------------------------------------------------------------------------
// Kernel 2: per-row softmax weights (one thread per row). Dedup + leaky-relu
// + softmax over <=8 unique neighbors (mask -9e15 underflows to exact 0).
// ---------------------------------------------------------------------------
__global__ __launch_bounds__(256) void gat_weights(const int* __restrict__ edges)
{
    const int g = blockIdx.x * 256 + threadIdx.x;
    const int b = g >> 10;
    const float* s2b = g_s2 + (b << 10);

    const int4 ea = __ldg(&((const int4*)edges)[2 * g]);
    const int4 eb = __ldg(&((const int4*)edges)[2 * g + 1]);
    int e[DEG] = { ea.x & (Nn - 1), ea.y & (Nn - 1), ea.z & (Nn - 1), ea.w & (Nn - 1),
                   eb.x & (Nn - 1), eb.y & (Nn - 1), eb.z & (Nn - 1), eb.w & (Nn - 1) };

    const float s1g = g_s1[g];

    float w[DEG];
    float mx = -1e30f;
    #pragma unroll
    for (int m = 0; m < DEG; m++) {
        float ev = s1g + __ldg(&s2b[e[m]]);
        ev = ev > 0.f ? ev : ALPHA * ev;
        bool dup = false;
        #pragma unroll
        for (int n = 0; n < m; n++) dup = dup || (e[n] == e[m]);
        w[m] = dup ? -1e30f : ev;
        mx = fmaxf(mx, w[m]);
    }
    float den = 0.f;
    #pragma unroll
    for (int m = 0; m < DEG; m++) {
        w[m] = (w[m] == -1e30f) ? 0.f : __expf(w[m] - mx);
        den += w[m];
    }
    const float inv = 1.f / den;

    ((float4*)g_w)[2 * g]     = make_float4(w[0] * inv, w[1] * inv, w[2] * inv, w[3] * inv);
    ((float4*)g_w)[2 * g + 1] = make_float4(w[4] * inv, w[5] * inv, w[6] * inv, w[7] * inv);
}

// ---------------------------------------------------------------------------
// Kernel 3: aggregation, two rows per warp (16 gathers in flight).
// ---------------------------------------------------------------------------
__global__ __launch_bounds__(256) void gat_agg(const int* __restrict__ edges,
                                               float* __restrict__ out)
{
    const int wid  = (blockIdx.x * 256 + threadIdx.x) >> 5;
    const int lane = threadIdx.x & 31;
    const int g0   = wid * 2;
    const int b    = g0 >> 10;

    const __half2* hb = g_h2 + ((size_t)b << 15);

    const float4 wa0 = __ldg(&((const float4*)g_w)[2 * g0]);
    const float4 wb0 = __ldg(&((const float4*)g_w)[2 * g0 + 1]);
    const float4 wa1 = __ldg(&((const float4*)g_w)[2 * g0 + 2]);
    const float4 wb1 = __ldg(&((const float4*)g_w)[2 * g0 + 3]);
    const int4 ea0 = __ldg(&((const int4*)edges)[2 * g0]);
    const int4 eb0 = __ldg(&((const int4*)edges)[2 * g0 + 1]);
    const int4 ea1 = __ldg(&((const int4*)edges)[2 * g0 + 2]);
    const int4 eb1 = __ldg(&((const int4*)edges)[2 * g0 + 3]);

    float2 acc0 = make_float2(0.f, 0.f);
    float2 acc1 = make_float2(0.f, 0.f);
    #define GSTEP(ACC, E, Wv) { \
        const float2 hv = __half22float2(__ldg(&hb[(size_t)((E) & (Nn - 1)) * 32 + lane])); \
        ACC.x = fmaf((Wv), hv.x, ACC.x); \
        ACC.y = fmaf((Wv), hv.y, ACC.y); }
    GSTEP(acc0, ea0.x, wa0.x) GSTEP(acc1, ea1.x, wa1.x)
    GSTEP(acc0, ea0.y, wa0.y) GSTEP(acc1, ea1.y, wa1.y)
    GSTEP(acc0, ea0.z, wa0.z) GSTEP(acc1, ea1.z, wa1.z)
    GSTEP(acc0, ea0.w, wa0.w) GSTEP(acc1, ea1.w, wa1.w)
    GSTEP(acc0, eb0.x, wb0.x) GSTEP(acc1, eb1.x, wb1.x)
    GSTEP(acc0, eb0.y, wb0.y) GSTEP(acc1, eb1.y, wb1.y)
    GSTEP(acc0, eb0.z, wb0.z) GSTEP(acc1, eb1.z, wb1.z)
    GSTEP(acc0, eb0.w, wb0.w) GSTEP(acc1, eb1.w, wb1.w)
    #undef GSTEP

    float2 o0, o1;
    o0.x = acc0.x > 0.f ? acc0.x : (__expf(acc0.x) - 1.f);
    o0.y = acc0.y > 0.f ? acc0.y : (__expf(acc0.y) - 1.f);
    o1.x = acc1.x > 0.f ? acc1.x : (__expf(acc1.x) - 1.f);
    o1.y = acc1.y > 0.f ? acc1.y : (__expf(acc1.y) - 1.f);
    ((float2*)out)[(size_t)g0 * 32 + lane]       = o0;
    ((float2*)out)[(size_t)(g0 + 1) * 32 + lane] = o1;
}

// ---------------------------------------------------------------------------
extern "C" void kernel_launch(void* const* d_in, const int* in_sizes, int n_in,
                              void* d_out, int out_size) {
    // Bind inputs BY ELEMENT COUNT (all four sizes distinct) — order-proof.
    const float* atoms = nullptr;   // 64*1024*64 = 4194304 (f32)
    const int*   edges = nullptr;   // 64*1024*8  = 524288  (i32: jax x64 off)
    const float* W     = nullptr;   // 64*64      = 4096    (f32)
    const float* a     = nullptr;   // 2*64*1     = 128     (f32)

    for (int i = 0; i < n_in; i++) {
        switch (in_sizes[i]) {
            case 4194304: atoms = (const float*)d_in[i]; break;
            case 524288:  edges = (const int*)d_in[i];   break;
            case 4096:    W     = (const float*)d_in[i]; break;
            case 128:     a     = (const float*)d_in[i]; break;
            default: break;
        }
    }
    if (!atoms || !edges || !W || !a) return;

    float* out = (float*)d_out;

    const int smem = (64 * SAT_PITCH + 64 * 64) * sizeof(float);  // 82944 B
    cudaFuncSetAttribute(gat_gemm, cudaFuncAttributeMaxDynamicSharedMemorySize, smem);

    gat_gemm<<<(Bb * Nn) / 256, 256, smem>>>(atoms, W, a);
    gat_weights<<<(Bb * Nn) / 256, 256>>>(edges);
    gat_agg<<<(Bb * Nn) / 2 / 8, 256>>>(edges, out);
}